// round 15
// baseline (speedup 1.0000x reference)
#include <cuda_runtime.h>
#include <cuda_bf16.h>
#include <cstdint>

// Problem constants (fixed by reference)
#define N_NODES 10000
#define N_EDGES 640000
#define D_IN    128
#define D_HID   256
#define D_OUT   64
#define CAP     192   // per-node edge-slot capacity; deg ~ Poisson(64), P(>192) ~ 0

typedef unsigned long long ull;

// ---------------------------------------------------------------------------
// Scratch (device globals — no allocation allowed)
// ---------------------------------------------------------------------------
__device__ int   g_cursor[N_NODES];
__device__ int2  g_edge[N_NODES * CAP];      // {src, __float_as_int(w)} per slot
__device__ float g_hN1[N_NODES * D_IN];      // layer-1 aggregated neighbor feats
__device__ float g_p1a[N_NODES * D_HID];     // h @ W1[0:128]  (self half, off-path)
__device__ float g_x1 [N_NODES * D_HID];     // layer-1 output (post relu)
__device__ float g_yS2[N_NODES * D_OUT];     // x1 @ W2_top (self term)
__device__ float g_y2 [N_NODES * D_OUT];     // x1 @ W2_bot (pre-aggregation)

// ---------------------------------------------------------------------------
// packed f32x2 helpers (FFMA2 path — 2x fp32 FMA rate, PTX-only)
// ---------------------------------------------------------------------------
__device__ __forceinline__ ull pack2(float x) {
    ull r;
    asm("mov.b64 %0, {%1, %1};" : "=l"(r) : "f"(x));
    return r;
}
__device__ __forceinline__ void fma2(ull& d, ull a, ull b) {
    asm("fma.rn.f32x2 %0, %1, %2, %0;" : "+l"(d) : "l"(a), "l"(b));
}
__device__ __forceinline__ float2 unpack2(ull v) {
    float2 f;
    asm("mov.b64 {%0, %1}, %2;" : "=f"(f.x), "=f"(f.y) : "l"(v));
    return f;
}

// ---------------------------------------------------------------------------
// Bucket fill: 4 edges per thread (int4/float4 loads -> MLP=4 atomic chains).
// ---------------------------------------------------------------------------
__global__ void k_fill(const int4* __restrict__ dst4,
                       const int4* __restrict__ src4,
                       const float4* __restrict__ w4) {
    int t = blockIdx.x * blockDim.x + threadIdx.x;
    if (t >= N_EDGES / 4) return;
    int4   d  = __ldg(&dst4[t]);
    int4   s  = __ldg(&src4[t]);
    float4 wv = __ldg(&w4[t]);
    int p;
    p = atomicAdd(&g_cursor[d.x], 1); g_edge[d.x * CAP + p] = make_int2(s.x, __float_as_int(wv.x));
    p = atomicAdd(&g_cursor[d.y], 1); g_edge[d.y * CAP + p] = make_int2(s.y, __float_as_int(wv.y));
    p = atomicAdd(&g_cursor[d.z], 1); g_edge[d.z * CAP + p] = make_int2(s.z, __float_as_int(wv.z));
    p = atomicAdd(&g_cursor[d.w], 1); g_edge[d.w * CAP + p] = make_int2(s.w, __float_as_int(wv.w));
}

// ---------------------------------------------------------------------------
// agg1: one warp per node, lane = float4 slice of D_IN=128 (near LTS floor).
// ---------------------------------------------------------------------------
__global__ __launch_bounds__(256) void k_agg1(const float* __restrict__ x,
                                              float* __restrict__ out) {
    int gw   = (blockIdx.x * blockDim.x + threadIdx.x) >> 5;
    int lane = threadIdx.x & 31;
    if (gw >= N_NODES) return;

    int deg = g_cursor[gw];
    const int2* ep = &g_edge[(size_t)gw * CAP];

    float4 acc = make_float4(0.f, 0.f, 0.f, 0.f);
    int p = 0;
    for (; p + 1 < deg; p += 2) {
        int4 rec = __ldg((const int4*)(ep + p));          // {s0,w0,s1,w1}
        float w0 = __int_as_float(rec.y);
        float w1 = __int_as_float(rec.w);
        float4 r0 = __ldg((const float4*)(x + (size_t)rec.x * D_IN) + lane);
        float4 r1 = __ldg((const float4*)(x + (size_t)rec.z * D_IN) + lane);
        acc.x = fmaf(r0.x, w0, acc.x); acc.y = fmaf(r0.y, w0, acc.y);
        acc.z = fmaf(r0.z, w0, acc.z); acc.w = fmaf(r0.w, w0, acc.w);
        acc.x = fmaf(r1.x, w1, acc.x); acc.y = fmaf(r1.y, w1, acc.y);
        acc.z = fmaf(r1.z, w1, acc.z); acc.w = fmaf(r1.w, w1, acc.w);
    }
    if (p < deg) {
        int2 cur = __ldg(&ep[p]);
        float we = __int_as_float(cur.y);
        float4 r = __ldg((const float4*)(x + (size_t)cur.x * D_IN) + lane);
        acc.x = fmaf(r.x, we, acc.x); acc.y = fmaf(r.y, we, acc.y);
        acc.z = fmaf(r.z, we, acc.z); acc.w = fmaf(r.w, we, acc.w);
    }
    float inv = (deg > 0) ? (1.0f / (float)deg) : 0.0f;
    acc.x *= inv; acc.y *= inv; acc.z *= inv; acc.w *= inv;
    ((float4*)(out + (size_t)gw * D_IN))[lane] = acc;
}

// ---------------------------------------------------------------------------
// agg2 + fused epilogue: lane = float2 slice of D_OUT=64, 2-edge unroll.
//   out[n] = yS[n] + (sum_e y2[src_e] * w_e)/max(deg,1) + b2
// ---------------------------------------------------------------------------
__global__ __launch_bounds__(256) void k_agg2(const float* __restrict__ y2,
                                              const float* __restrict__ yS,
                                              const float* __restrict__ b2,
                                              float* __restrict__ out) {
    int gw   = (blockIdx.x * blockDim.x + threadIdx.x) >> 5;
    int lane = threadIdx.x & 31;
    if (gw >= N_NODES) return;

    int deg = g_cursor[gw];
    const int2* ep = &g_edge[(size_t)gw * CAP];

    float2 acc = make_float2(0.f, 0.f);
    int p = 0;
    for (; p + 1 < deg; p += 2) {
        int4 rec = __ldg((const int4*)(ep + p));
        float w0 = __int_as_float(rec.y);
        float w1 = __int_as_float(rec.w);
        float2 r0 = __ldg((const float2*)(y2 + (size_t)rec.x * D_OUT) + lane);
        float2 r1 = __ldg((const float2*)(y2 + (size_t)rec.z * D_OUT) + lane);
        acc.x = fmaf(r0.x, w0, acc.x); acc.y = fmaf(r0.y, w0, acc.y);
        acc.x = fmaf(r1.x, w1, acc.x); acc.y = fmaf(r1.y, w1, acc.y);
    }
    if (p < deg) {
        int2 cur = __ldg(&ep[p]);
        float we = __int_as_float(cur.y);
        float2 r = __ldg((const float2*)(y2 + (size_t)cur.x * D_OUT) + lane);
        acc.x = fmaf(r.x, we, acc.x); acc.y = fmaf(r.y, we, acc.y);
    }
    float inv = (deg > 0) ? (1.0f / (float)deg) : 0.0f;
    float2 s  = ((const float2*)(yS + (size_t)gw * D_OUT))[lane];
    float2 bb = ((const float2*)b2)[lane];
    float2 o;
    o.x = fmaf(acc.x, inv, s.x) + bb.x;
    o.y = fmaf(acc.y, inv, s.y) + bb.y;
    ((float2*)(out + (size_t)gw * D_OUT))[lane] = o;
}

// ---------------------------------------------------------------------------
// GEMM1 half (K=128): out = A @ Wb (+ padd + bias, relu if FUSE)
//   FUSE=false: p1a = h   @ W1[0:128]    (side stream, off critical path)
//   FUSE=true : x1  = relu(hN1 @ W1[128:256] + p1a + b1)
// BM=32 BN=64 BK=16 TM=4 TN=4, 128 threads, grid (4, 313) = 1252 blocks.
// ---------------------------------------------------------------------------
template <bool FUSE>
__global__ __launch_bounds__(128) void k_gemm1(
        const float* __restrict__ A,     // [M,128]
        const float* __restrict__ Wb,    // [128,256] slice
        const float* __restrict__ padd,  // [M,256] (FUSE only)
        const float* __restrict__ bias,  // [256]   (FUSE only)
        float* __restrict__ out,         // [M,256]
        int M) {
    __shared__ float sA[2][16][36];
    __shared__ float sB[2][16][64];
    int tid = threadIdx.x;
    int tx  = tid & 15;    // 0..15 (BN/TN)
    int ty  = tid >> 4;    // 0..7  (BM/TM)
    int rowBase = blockIdx.y * 32;
    int colBase = blockIdx.x * 64;

    ull acc[2][4];   // [row-pair][col]
    #pragma unroll
    for (int i = 0; i < 2; i++)
        #pragma unroll
        for (int j = 0; j < 4; j++) acc[i][j] = 0ULL;

    float4 pa, pb[2];

    auto loadTiles = [&](int kt) {
        {
            int r  = tid >> 2;            // 0..31
            int s4 = tid & 3;             // 0..3
            int gr = rowBase + r;
            pa = (gr < M) ? *(const float4*)(A + (size_t)gr * D_IN + kt + s4 * 4)
                          : make_float4(0.f, 0.f, 0.f, 0.f);
        }
        #pragma unroll
        for (int t = 0; t < 2; t++) {
            int i  = tid + t * 128;       // 0..255
            int r  = i >> 4;              // 0..15
            int c4 = i & 15;              // 0..15
            pb[t] = *(const float4*)(Wb + (size_t)(kt + r) * D_HID + colBase + c4 * 4);
        }
    };
    auto storeTiles = [&](int b) {
        {
            int r  = tid >> 2;
            int s4 = tid & 3;
            sA[b][s4 * 4 + 0][r] = pa.x;
            sA[b][s4 * 4 + 1][r] = pa.y;
            sA[b][s4 * 4 + 2][r] = pa.z;
            sA[b][s4 * 4 + 3][r] = pa.w;
        }
        #pragma unroll
        for (int t = 0; t < 2; t++) {
            int i  = tid + t * 128;
            int r  = i >> 4;
            int c4 = i & 15;
            *(float4*)&sB[b][r][c4 * 4] = pb[t];
        }
    };

    constexpr int NIT = D_IN / 16;   // 8
    loadTiles(0);
    storeTiles(0);
    __syncthreads();

    for (int it = 0; it < NIT; it++) {
        int b = it & 1;
        if (it + 1 < NIT) loadTiles((it + 1) * 16);
        #pragma unroll
        for (int k = 0; k < 16; k++) {
            const ull* pA = (const ull*)&sA[b][k][ty * 4];
            ull a0 = pA[0];
            ull a1 = pA[1];
            #pragma unroll
            for (int j = 0; j < 4; j++) {
                ull bb = pack2(sB[b][k][tx * 4 + j]);
                fma2(acc[0][j], a0, bb);
                fma2(acc[1][j], a1, bb);
            }
        }
        __syncthreads();
        if (it + 1 < NIT) {
            storeTiles(b ^ 1);
            __syncthreads();
        }
    }

    #pragma unroll
    for (int i = 0; i < 2; i++) {
        int gr0 = rowBase + ty * 4 + 2 * i;
        #pragma unroll
        for (int j = 0; j < 4; j++) {
            int gc = colBase + tx * 4 + j;
            float2 v = unpack2(acc[i][j]);
            if (FUSE) {
                float b = bias[gc];
                if (gr0 < M)
                    out[(size_t)gr0 * D_HID + gc] =
                        fmaxf(v.x + padd[(size_t)gr0 * D_HID + gc] + b, 0.f);
                if (gr0 + 1 < M)
                    out[(size_t)(gr0 + 1) * D_HID + gc] =
                        fmaxf(v.y + padd[(size_t)(gr0 + 1) * D_HID + gc] + b, 0.f);
            } else {
                if (gr0 < M)     out[(size_t)gr0 * D_HID + gc]       = v.x;
                if (gr0 + 1 < M) out[(size_t)(gr0 + 1) * D_HID + gc] = v.y;
            }
        }
    }
}

// ---------------------------------------------------------------------------
// GEMM2: blockIdx.x = half (0: yS = x1@W2[0:256], 1: y2 = x1@W2[256:512]).
// BM=16 BN=64 BK=32 TM=2 TN=4, 128 threads, grid (2, 625) = 1250 blocks.
// ---------------------------------------------------------------------------
__global__ __launch_bounds__(128) void k_gemm2(
        const float* __restrict__ A,    // x1 [M,256]
        const float* __restrict__ W2,   // [512,64]
        float* __restrict__ yS,         // [M,64]
        float* __restrict__ y2,         // [M,64]
        int M) {
    __shared__ float sA[2][32][20];
    __shared__ float sB[2][32][64];
    int tid = threadIdx.x;
    int tx  = tid & 15;    // 0..15 (BN/TN)
    int ty  = tid >> 4;    // 0..7  (BM/TM)
    int rowBase = blockIdx.y * 16;
    const float* Wb = W2 + (size_t)blockIdx.x * D_HID * D_OUT;

    ull acc[4];
    #pragma unroll
    for (int j = 0; j < 4; j++) acc[j] = 0ULL;

    float4 pa, pb[4];

    auto loadTiles = [&](int kt) {
        {
            int r  = tid >> 3;           // 0..15
            int s4 = tid & 7;            // 0..7
            int gr = rowBase + r;
            pa = (gr < M) ? *(const float4*)(A + (size_t)gr * D_HID + kt + s4 * 4)
                          : make_float4(0.f, 0.f, 0.f, 0.f);
        }
        #pragma unroll
        for (int t = 0; t < 4; t++) {
            int i  = tid + t * 128;      // 0..511
            int r  = i >> 4;             // 0..31
            int c4 = i & 15;             // 0..15
            pb[t] = *(const float4*)(Wb + (size_t)(kt + r) * D_OUT + c4 * 4);
        }
    };
    auto storeTiles = [&](int b) {
        {
            int r  = tid >> 3;
            int s4 = tid & 7;
            sA[b][s4 * 4 + 0][r] = pa.x;
            sA[b][s4 * 4 + 1][r] = pa.y;
            sA[b][s4 * 4 + 2][r] = pa.z;
            sA[b][s4 * 4 + 3][r] = pa.w;
        }
        #pragma unroll
        for (int t = 0; t < 4; t++) {
            int i  = tid + t * 128;
            int r  = i >> 4;
            int c4 = i & 15;
            *(float4*)&sB[b][r][c4 * 4] = pb[t];
        }
    };

    constexpr int NIT = D_HID / 32;   // 8
    loadTiles(0);
    storeTiles(0);
    __syncthreads();

    for (int it = 0; it < NIT; it++) {
        int b = it & 1;
        if (it + 1 < NIT) loadTiles((it + 1) * 32);
        #pragma unroll
        for (int k = 0; k < 32; k++) {
            ull a0 = *(const ull*)&sA[b][k][ty * 2];
            #pragma unroll
            for (int j = 0; j < 4; j++) {
                ull bb = pack2(sB[b][k][tx * 4 + j]);
                fma2(acc[j], a0, bb);
            }
        }
        __syncthreads();
        if (it + 1 < NIT) {
            storeTiles(b ^ 1);
            __syncthreads();
        }
    }

    float* outp = (blockIdx.x == 0) ? yS : y2;
    int gr0 = rowBase + ty * 2;
    #pragma unroll
    for (int j = 0; j < 4; j++) {
        int gc = tx * 4 + j;
        float2 v = unpack2(acc[j]);
        if (gr0 < M)     outp[(size_t)gr0 * D_OUT + gc]       = v.x;
        if (gr0 + 1 < M) outp[(size_t)(gr0 + 1) * D_OUT + gc] = v.y;
    }
}

// ---------------------------------------------------------------------------
// launch — forked-stream graph:
//   S0: memset -> fill -> agg1 -> [wait evA] gemm1b -> gemm2 -> agg2
//   S1: gemm1a (h @ W1_top, no deps) -> evA
// ---------------------------------------------------------------------------
extern "C" void kernel_launch(void* const* d_in, const int* in_sizes, int n_in,
                              void* d_out, int out_size) {
    const float* h   = (const float*)d_in[0];   // [N, 128]
    const float* w   = (const float*)d_in[1];   // [E, 1]
    const int*   src = (const int*)  d_in[2];   // [E]
    const int*   dst = (const int*)  d_in[3];   // [E]
    const float* W1  = (const float*)d_in[4];   // [256, 256]
    const float* b1  = (const float*)d_in[5];   // [256]
    const float* W2  = (const float*)d_in[6];   // [512, 64]
    const float* b2  = (const float*)d_in[7];   // [64]
    float* out = (float*)d_out;                 // [N, 64]

    float *hN1, *p1a, *x1, *yS2, *y2;
    int* cursor;
    cudaGetSymbolAddress((void**)&hN1,    g_hN1);
    cudaGetSymbolAddress((void**)&p1a,    g_p1a);
    cudaGetSymbolAddress((void**)&x1,     g_x1);
    cudaGetSymbolAddress((void**)&yS2,    g_yS2);
    cudaGetSymbolAddress((void**)&y2,     g_y2);
    cudaGetSymbolAddress((void**)&cursor, g_cursor);

    // Lazily-created side stream + events (host resources only, no device mem).
    // Created on the first (non-capture, correctness) call; reused thereafter.
    static cudaStream_t s1 = nullptr;
    static cudaEvent_t evFork = nullptr, evA = nullptr;
    if (s1 == nullptr) {
        cudaStreamCreateWithFlags(&s1, cudaStreamNonBlocking);
        cudaEventCreateWithFlags(&evFork, cudaEventDisableTiming);
        cudaEventCreateWithFlags(&evA,   cudaEventDisableTiming);
    }

    const int aggBlocks = (N_NODES * 32 + 255) / 256;  // 1250, 1 warp per node
    const dim3 grd1(D_HID / 64, (N_NODES + 31) / 32);  // (4, 313)
    const dim3 grd2(2, (N_NODES + 15) / 16);           // (2, 625)

    // --- fork: side stream computes the graph-independent self half ---
    cudaEventRecord(evFork, 0);
    cudaStreamWaitEvent(s1, evFork, 0);
    k_gemm1<false><<<grd1, 128, 0, s1>>>(h, W1, nullptr, nullptr, p1a, N_NODES);
    cudaEventRecord(evA, s1);

    // --- main stream: bucket build + layer-1 aggregation ---
    cudaMemsetAsync(cursor, 0, N_NODES * sizeof(int));
    k_fill<<<(N_EDGES / 4 + 255) / 256, 256>>>(
        (const int4*)dst, (const int4*)src, (const float4*)w);
    k_agg1<<<aggBlocks, 256>>>(h, hN1);

    // --- join, then fused neighbor half: x1 = relu(hN1 @ W1_bot + p1a + b1) ---
    cudaStreamWaitEvent(0, evA, 0);
    k_gemm1<true><<<grd1, 128>>>(hN1, W1 + (size_t)D_IN * D_HID, p1a, b1, x1,
                                 N_NODES);

    // --- Layer 2 (re-associated): dual projection, then agg + epilogue ---
    k_gemm2<<<grd2, 128>>>(x1, W2, yS2, y2, N_NODES);
    k_agg2<<<aggBlocks, 256>>>(y2, yS2, b2, out);
}